// round 16
// baseline (speedup 1.0000x reference)
#include <cuda_runtime.h>
#include <cuda_fp16.h>
#include <math.h>
#include <stdint.h>

// ---------------- problem constants ----------------
#define T_TOK 4096
#define D_DIM 1024
#define E_NUM 8
#define F_DIM 4096
#define G1_N  256
#define G2_N  64
#define MAXPAIRS (T_TOK * 2)

// ---------------- device scratch (no allocs allowed) ----------------
__device__ float  g_g1[T_TOK * G1_N];
__device__ __half g_acth[(size_t)MAXPAIRS * F_DIM];         // 64 MB fp16 activations
__device__ __half g_hh[(size_t)T_TOK * D_DIM];              // 8 MB fp16 hidden states
__device__ __half g_w1t[(size_t)E_NUM * F_DIM * D_DIM];     // 64 MB [e][F][D]
__device__ __half g_w2t[(size_t)E_NUM * D_DIM * F_DIM];     // 64 MB [e][D][F]
__device__ int    g_topi[T_TOK * 2];
__device__ float  g_topw[T_TOK * 2];
__device__ int    g_pair_token[MAXPAIRS];
__device__ float  g_pair_w[MAXPAIRS];
__device__ int    g_counts[E_NUM];
__device__ int    g_offsets[E_NUM];

// ---------------- helpers ----------------
__device__ __forceinline__ float gelu_tanh(float x) {
    float x3 = x * x * x;
    float u = 0.7978845608028654f * (x + 0.044715f * x3);
    return 0.5f * x * (1.0f + tanhf(u));
}

__device__ __forceinline__ uint32_t smem_u32(const void* p) {
    uint32_t a;
    asm("{ .reg .u64 t; cvta.to.shared.u64 t, %1; cvt.u32.u64 %0, t; }" : "=r"(a) : "l"(p));
    return a;
}

__device__ __forceinline__ void cpasync16(uint32_t s, const void* g) {
    asm volatile("cp.async.cg.shared.global [%0], [%1], 16;" :: "r"(s), "l"(g));
}
#define CP_COMMIT() asm volatile("cp.async.commit_group;" ::: "memory")
#define CP_WAIT0()  asm volatile("cp.async.wait_group 0;" ::: "memory")
#define CP_WAIT1()  asm volatile("cp.async.wait_group 1;" ::: "memory")

__device__ __forceinline__ void mma16816(float* d, const uint32_t* a, const uint32_t* b) {
    asm volatile(
        "mma.sync.aligned.m16n8k16.row.col.f32.f16.f16.f32 "
        "{%0,%1,%2,%3}, {%4,%5,%6,%7}, {%8,%9}, {%0,%1,%2,%3};\n"
        : "+f"(d[0]), "+f"(d[1]), "+f"(d[2]), "+f"(d[3])
        : "r"(a[0]), "r"(a[1]), "r"(a[2]), "r"(a[3]), "r"(b[0]), "r"(b[1]));
}

__device__ __forceinline__ void ldsm4(uint32_t& r0, uint32_t& r1, uint32_t& r2, uint32_t& r3,
                                      uint32_t addr) {
    asm volatile("ldmatrix.sync.aligned.m8n8.x4.shared.b16 {%0,%1,%2,%3}, [%4];"
                 : "=r"(r0), "=r"(r1), "=r"(r2), "=r"(r3) : "r"(addr));
}

// ---------------- zero output ----------------
__global__ void zero_out_kernel(float* __restrict__ out, int n4) {
    int i = blockIdx.x * blockDim.x + threadIdx.x;
    if (i < n4) ((float4*)out)[i] = make_float4(0.f, 0.f, 0.f, 0.f);
}

// ---------------- one-time fp32 -> fp16 conversions ----------------
__global__ void f2h_kernel(const float* __restrict__ in, __half* __restrict__ out, int n4) {
    int i = blockIdx.x * blockDim.x + threadIdx.x;
    if (i < n4) {
        float4 v = ((const float4*)in)[i];
        ((__half2*)out)[2 * i + 0] = __floats2half2_rn(v.x, v.y);
        ((__half2*)out)[2 * i + 1] = __floats2half2_rn(v.z, v.w);
    }
}

// batched transpose: in [R][C] fp32 row-major -> out [C][R] fp16 (z = batch)
__global__ void transpose_f2h(const float* __restrict__ in, __half* __restrict__ out,
                              int R, int C) {
    __shared__ float t[32][33];
    size_t base = (size_t)blockIdx.z * R * C;
    int x = blockIdx.x * 32 + threadIdx.x;
    int y = blockIdx.y * 32 + threadIdx.y;
    #pragma unroll
    for (int j = 0; j < 32; j += 8)
        t[threadIdx.y + j][threadIdx.x] = in[base + (size_t)(y + j) * C + x];
    __syncthreads();
    int ox = blockIdx.y * 32 + threadIdx.x;
    int oy = blockIdx.x * 32 + threadIdx.y;
    #pragma unroll
    for (int j = 0; j < 32; j += 8)
        out[base + (size_t)(oy + j) * R + ox] = __float2half_rn(t[threadIdx.x][threadIdx.y + j]);
}

// ---------------- router layer 1: exact fp32, 64x64 tiles ----------------
__global__ void __launch_bounds__(256)
gemm64_bias_relu(const float* __restrict__ A, const float* __restrict__ B,
                 const float* __restrict__ bias, float* __restrict__ C,
                 int M, int N, int K) {
    const int BKr = 16;
    __shared__ float As[BKr][64];
    __shared__ float Bs[BKr][64];
    int tid = threadIdx.x;
    int m0 = blockIdx.y * 64, n0 = blockIdx.x * 64;
    int tx = tid & 15, ty = tid >> 4;
    int arow = tid >> 2, ac4 = (tid & 3) * 4;
    int brow = tid >> 4, bc4 = (tid & 15) * 4;
    float acc[4][4];
    #pragma unroll
    for (int i = 0; i < 4; i++)
        #pragma unroll
        for (int j = 0; j < 4; j++) acc[i][j] = 0.f;

    const float* aptr = A + (size_t)(m0 + arow) * K + ac4;
    const float* bptr = B + (size_t)brow * N + n0 + bc4;
    for (int k0 = 0; k0 < K; k0 += BKr) {
        float4 av = *(const float4*)(aptr + k0);
        As[ac4 + 0][arow] = av.x; As[ac4 + 1][arow] = av.y;
        As[ac4 + 2][arow] = av.z; As[ac4 + 3][arow] = av.w;
        float4 bv = *(const float4*)(bptr + (size_t)k0 * N);
        *(float4*)&Bs[brow][bc4] = bv;
        __syncthreads();
        #pragma unroll
        for (int k = 0; k < BKr; k++) {
            float ra[4], rb[4];
            #pragma unroll
            for (int i = 0; i < 4; i++) ra[i] = As[k][ty * 4 + i];
            #pragma unroll
            for (int j = 0; j < 4; j++) rb[j] = Bs[k][tx * 4 + j];
            #pragma unroll
            for (int i = 0; i < 4; i++)
                #pragma unroll
                for (int j = 0; j < 4; j++) acc[i][j] = fmaf(ra[i], rb[j], acc[i][j]);
        }
        __syncthreads();
    }
    #pragma unroll
    for (int i = 0; i < 4; i++) {
        int m = m0 + ty * 4 + i;
        #pragma unroll
        for (int j = 0; j < 4; j++) {
            int n = n0 + tx * 4 + j;
            C[(size_t)m * N + n] = fmaxf(acc[i][j] + bias[n], 0.f);
        }
    }
}

// ---------------- fused router layer 2 + logits + top-2 (exact fp32) -----
// 64 tokens per CTA, 256 threads (4 threads per token, 16 n-outputs each),
// grid = T/64 = 64. Smem: g1 tile [64][132] + w2 tile [128][68].
#define RT_G1P 132
#define RT_W2P 68
#define RT_SMEM ((64 * RT_G1P + 128 * RT_W2P) * 4)

__global__ void __launch_bounds__(256)
router_l2_fused(const float* __restrict__ g1, const float* __restrict__ gw2,
                const float* __restrict__ gb2, const float* __restrict__ gw3,
                float* __restrict__ out_logits) {
    extern __shared__ float sm[];
    float* sG1 = sm;                     // [64][RT_G1P]
    float* sW2 = sm + 64 * RT_G1P;       // [128][RT_W2P]
    int tid = threadIdx.x;
    int tok0 = blockIdx.x * 64;
    int tok = tid >> 2;                  // 0..63
    int g = tid & 3;                     // 0..3  -> outputs n = g + 4j

    float acc[16];
    #pragma unroll
    for (int j = 0; j < 16; j++) acc[j] = 0.f;

    for (int kt = 0; kt < 2; kt++) {
        // stage g1 tile: 64 tokens x 128 k  (coalesced float4)
        for (int i = tid; i < 64 * 32; i += 256) {
            int r = i >> 5, c4 = i & 31;
            float4 v = *(const float4*)&g1[(size_t)(tok0 + r) * G1_N + kt * 128 + c4 * 4];
            *(float4*)&sG1[r * RT_G1P + c4 * 4] = v;
        }
        // stage w2 tile: 128 k x 64 n
        for (int i = tid; i < 128 * 16; i += 256) {
            int r = i >> 4, c4 = i & 15;
            float4 v = *(const float4*)&gw2[(size_t)(kt * 128 + r) * G2_N + c4 * 4];
            *(float4*)&sW2[r * RT_W2P + c4 * 4] = v;
        }
        __syncthreads();
        for (int k = 0; k < 128; k++) {
            float a = sG1[tok * RT_G1P + k];
            #pragma unroll
            for (int j = 0; j < 16; j++)
                acc[j] = fmaf(a, sW2[k * RT_W2P + g + 4 * j], acc[j]);
        }
        __syncthreads();
    }

    // g2 = relu(acc + gb2[n]); partial logits over this thread's 16 n's
    float l[E_NUM];
    #pragma unroll
    for (int e = 0; e < E_NUM; e++) l[e] = 0.f;
    #pragma unroll
    for (int j = 0; j < 16; j++) {
        int n = g + 4 * j;
        float v = fmaxf(acc[j] + gb2[n], 0.f);
        #pragma unroll
        for (int e = 0; e < E_NUM; e++)
            l[e] = fmaf(v, gw3[n * E_NUM + e], l[e]);
    }
    // reduce across the 4 lanes of this token (lanes tok*4+g are contiguous)
    #pragma unroll
    for (int e = 0; e < E_NUM; e++) {
        l[e] += __shfl_xor_sync(0xffffffffu, l[e], 1);
        l[e] += __shfl_xor_sync(0xffffffffu, l[e], 2);
    }
    if (g == 0) {
        int t = tok0 + tok;
        #pragma unroll
        for (int e = 0; e < E_NUM; e++) out_logits[(size_t)t * E_NUM + e] = l[e];
        int i0 = 0; float v0 = l[0];
        #pragma unroll
        for (int e = 1; e < E_NUM; e++) { if (l[e] > v0) { v0 = l[e]; i0 = e; } }
        int i1 = -1; float v1 = -3.4e38f;
        #pragma unroll
        for (int e = 0; e < E_NUM; e++) { if (e != i0 && l[e] > v1) { v1 = l[e]; i1 = e; } }
        float e1 = expf(v1 - v0);
        float inv = 1.f / (1.f + e1);
        g_topi[2 * t] = i0;  g_topi[2 * t + 1] = i1;
        g_topw[2 * t] = inv; g_topw[2 * t + 1] = e1 * inv;
    }
}

__global__ void build_pairs() {
    __shared__ int s_cnt[E_NUM];
    __shared__ int s_off[E_NUM];
    int tid = threadIdx.x, wid = tid >> 5, lane = tid & 31;
    if (wid < E_NUM) {
        int e = wid, cnt = 0;
        for (int base = 0; base < T_TOK; base += 32) {
            int t = base + lane;
            bool c = (g_topi[2 * t] == e) || (g_topi[2 * t + 1] == e);
            cnt += __popc(__ballot_sync(0xffffffffu, c));
        }
        if (lane == 0) s_cnt[e] = cnt;
    }
    __syncthreads();
    if (tid == 0) {
        int off = 0;
        for (int e = 0; e < E_NUM; e++) {
            s_off[e] = off; g_offsets[e] = off; g_counts[e] = s_cnt[e];
            off += s_cnt[e];
        }
    }
    __syncthreads();
    if (wid < E_NUM) {
        int e = wid, pos = s_off[e];
        for (int base = 0; base < T_TOK; base += 32) {
            int t = base + lane;
            bool c0 = (g_topi[2 * t] == e);
            bool c  = c0 || (g_topi[2 * t + 1] == e);
            unsigned b = __ballot_sync(0xffffffffu, c);
            int idx = pos + __popc(b & ((1u << lane) - 1u));
            if (c) {
                g_pair_token[idx] = t;
                g_pair_w[idx] = c0 ? g_topw[2 * t] : g_topw[2 * t + 1];
            }
            pos += __popc(b);
        }
    }
}

// ======================================================================
// fp16 mma.sync expert GEMMs, 3-stage cp.async pipeline + ldmatrix.
// CTA tile 128x128, BK=32, 8 warps (2m x 4n), warp tile 64x32.
// Dynamic smem: 3 stages x (A,B) 128x40 halves = 60 KB. 2 CTAs/SM.
// R7-proven loop: wait -> __syncthreads -> prefetch(kt+2) -> compute(kt).
// ======================================================================
#define BK   32
#define KPAD 40
#define TILEB (128 * KPAD * 2)            // bytes per operand per stage
#define SMEM_EXP (6 * TILEB)              // 3 stages x (A + B)

// one BK=32 k-tile of MMAs from stage buffers (ldmatrix fragments)
__device__ __forceinline__ void mma_ktile_ldsm(uint32_t aAddr, uint32_t bAddr,
                                               float acc[4][4][4]) {
    #pragma unroll
    for (int kk = 0; kk < BK; kk += 16) {
        uint32_t a[4][4], b[4][2];
        #pragma unroll
        for (int im = 0; im < 4; im++)
            ldsm4(a[im][0], a[im][1], a[im][2], a[im][3],
                  aAddr + (uint32_t)((im * 16 * KPAD + kk) * 2));
        ldsm4(b[0][0], b[0][1], b[1][0], b[1][1], bAddr + (uint32_t)(kk * 2));
        ldsm4(b[2][0], b[2][1], b[3][0], b[3][1],
              bAddr + (uint32_t)((16 * KPAD + kk) * 2));
        #pragma unroll
        for (int im = 0; im < 4; im++)
            #pragma unroll
            for (int jn = 0; jn < 4; jn++)
                mma16816(acc[im][jn], a[im], b[jn]);
    }
}

// ---------------- pass A: act = gelu(gather(hh) @ w1t[e]^T + b1[e]) ------
__global__ void __launch_bounds__(256, 2)
expert_g1_fp16(const __half* __restrict__ w1t, const float* __restrict__ b1) {
    extern __shared__ char smemraw[];
    int gt = blockIdx.y;
    int e = gt >> 5;
    int m0 = (gt & 31) * 128;
    int cnt = g_counts[e];
    if (m0 >= cnt) return;
    int off = g_offsets[e];
    int n0 = blockIdx.x * 128;
    const __half* Bt = w1t + (size_t)e * F_DIM * D_DIM;

    int tid = threadIdx.x, lane = tid & 31, wid = tid >> 5;
    int warp_m = wid & 1, warp_n = wid >> 1;
    uint32_t sa = smem_u32(smemraw);

    int c0 = tid * 2, c1 = tid * 2 + 1;
    int ar0 = c0 >> 2, ac0 = c0 & 3;
    int ar1 = c1 >> 2, ac1 = c1 & 3;
    int p0 = (m0 + ar0 < cnt) ? off + m0 + ar0 : off;
    int p1 = (m0 + ar1 < cnt) ? off + m0 + ar1 : off;
    const __half* asrc0 = g_hh + (size_t)g_pair_token[p0] * D_DIM + ac0 * 8;
    const __half* asrc1 = g_hh + (size_t)g_pair_token[p1] * D_DIM + ac1 * 8;
    const __half* bsrc0 = Bt + (size_t)(n0 + ar0) * D_DIM + ac0 * 8;
    const __half* bsrc1 = Bt + (size_t)(n0 + ar1) * D_DIM + ac1 * 8;
    uint32_t adst0 = (uint32_t)(ar0 * KPAD + ac0 * 8) * 2;
    uint32_t adst1 = (uint32_t)(ar1 * KPAD + ac1 * 8) * 2;
    uint32_t bdst0 = 3 * TILEB + (uint32_t)(ar0 * KPAD + ac0 * 8) * 2;
    uint32_t bdst1 = 3 * TILEB + (uint32_t)(ar1 * KPAD + ac1 * 8) * 2;

    int a_row = lane & 15;
    int a_colh = (lane >> 4) * 8;
    uint32_t aBase = sa + (uint32_t)(((warp_m * 64 + a_row) * KPAD + a_colh) * 2);
    int b_row = (lane & 7) + ((lane >> 4) & 1) * 8;
    int b_colh = ((lane >> 3) & 1) * 8;
    uint32_t bBase = sa + 3 * TILEB + (uint32_t)(((warp_n * 32 + b_row) * KPAD + b_colh) * 2);

    float acc[4][4][4];
    #pragma unroll
    for (int im = 0; im < 4; im++)
        #pragma unroll
        for (int jn = 0; jn < 4; jn++)
            #pragma unroll
            for (int q = 0; q < 4; q++) acc[im][jn][q] = 0.f;

    const int NT = D_DIM / BK;
    #pragma unroll
    for (int s = 0; s < 2; s++) {
        int kb = s * BK;
        uint32_t so = (uint32_t)s * TILEB;
        cpasync16(sa + so + adst0, asrc0 + kb); cpasync16(sa + so + adst1, asrc1 + kb);
        cpasync16(sa + so + bdst0, bsrc0 + kb); cpasync16(sa + so + bdst1, bsrc1 + kb);
        CP_COMMIT();
    }

    for (int kt = 0; kt < NT; kt++) {
        if (kt + 1 < NT) { CP_WAIT1(); } else { CP_WAIT0(); }
        __syncthreads();
        if (kt + 2 < NT) {
            int s = (kt + 2) % 3;
            int kb = (kt + 2) * BK;
            uint32_t so = (uint32_t)s * TILEB;
            cpasync16(sa + so + adst0, asrc0 + kb); cpasync16(sa + so + adst1, asrc1 + kb);
            cpasync16(sa + so + bdst0, bsrc0 + kb); cpasync16(sa + so + bdst1, bsrc1 + kb);
            CP_COMMIT();
        }
        uint32_t so = (uint32_t)(kt % 3) * TILEB;
        mma_ktile_ldsm(aBase + so, bBase + so, acc);
    }

    // epilogue: gelu(acc + b1) -> g_acth (fp16)
    int g = lane >> 2, t2 = (lane & 3) * 2;
    #pragma unroll
    for (int im = 0; im < 4; im++) {
        #pragma unroll
        for (int hf = 0; hf < 2; hf++) {
            int mloc = warp_m * 64 + im * 16 + g + hf * 8;
            if (m0 + mloc < cnt) {
                size_t pi = (size_t)(off + m0 + mloc);
                #pragma unroll
                for (int jn = 0; jn < 4; jn++) {
                    int n = n0 + warp_n * 32 + jn * 8 + t2;
                    float vx = acc[im][jn][hf * 2 + 0] + b1[e * F_DIM + n + 0];
                    float vy = acc[im][jn][hf * 2 + 1] + b1[e * F_DIM + n + 1];
                    *(__half2*)&g_acth[pi * F_DIM + n] =
                        __floats2half2_rn(gelu_tanh(vx), gelu_tanh(vy));
                }
            }
        }
    }
}

// ---------------- pass B: out[token] += wt * (acth @ w2t[e]^T + b2[e]) ---
__global__ void __launch_bounds__(256, 2)
expert_g2_fp16(const __half* __restrict__ w2t, const float* __restrict__ b2,
               float* __restrict__ out) {
    extern __shared__ char smemraw[];
    int gt = blockIdx.y;
    int e = gt >> 5;
    int m0 = (gt & 31) * 128;
    int cnt = g_counts[e];
    if (m0 >= cnt) return;
    int off = g_offsets[e];
    int n0 = blockIdx.x * 128;
    const __half* Bt = w2t + (size_t)e * D_DIM * F_DIM;

    int tid = threadIdx.x, lane = tid & 31, wid = tid >> 5;
    int warp_m = wid & 1, warp_n = wid >> 1;
    uint32_t sa = smem_u32(smemraw);

    int c0 = tid * 2, c1 = tid * 2 + 1;
    int ar0 = c0 >> 2, ac0 = c0 & 3;
    int ar1 = c1 >> 2, ac1 = c1 & 3;
    size_t p0 = (size_t)((m0 + ar0 < cnt) ? off + m0 + ar0 : off);
    size_t p1 = (size_t)((m0 + ar1 < cnt) ? off + m0 + ar1 : off);
    const __half* asrc0 = g_acth + p0 * F_DIM + ac0 * 8;
    const __half* asrc1 = g_acth + p1 * F_DIM + ac1 * 8;
    const __half* bsrc0 = Bt + (size_t)(n0 + ar0) * F_DIM + ac0 * 8;
    const __half* bsrc1 = Bt + (size_t)(n0 + ar1) * F_DIM + ac1 * 8;
    uint32_t adst0 = (uint32_t)(ar0 * KPAD + ac0 * 8) * 2;
    uint32_t adst1 = (uint32_t)(ar1 * KPAD + ac1 * 8) * 2;
    uint32_t bdst0 = 3 * TILEB + (uint32_t)(ar0 * KPAD + ac0 * 8) * 2;
    uint32_t bdst1 = 3 * TILEB + (uint32_t)(ar1 * KPAD + ac1 * 8) * 2;

    int a_row = lane & 15;
    int a_colh = (lane >> 4) * 8;
    uint32_t aBase = sa + (uint32_t)(((warp_m * 64 + a_row) * KPAD + a_colh) * 2);
    int b_row = (lane & 7) + ((lane >> 4) & 1) * 8;
    int b_colh = ((lane >> 3) & 1) * 8;
    uint32_t bBase = sa + 3 * TILEB + (uint32_t)(((warp_n * 32 + b_row) * KPAD + b_colh) * 2);

    float acc[4][4][4];
    #pragma unroll
    for (int im = 0; im < 4; im++)
        #pragma unroll
        for (int jn = 0; jn < 4; jn++)
            #pragma unroll
            for (int q = 0; q < 4; q++) acc[im][jn][q] = 0.f;

    const int NT = F_DIM / BK;
    #pragma unroll
    for (int s = 0; s < 2; s++) {
        int kb = s * BK;
        uint32_t so = (uint32_t)s * TILEB;
        cpasync16(sa + so + adst0, asrc0 + kb); cpasync16(sa + so + adst1, asrc1 + kb);
        cpasync16(sa + so + bdst0, bsrc0 + kb); cpasync16(sa + so + bdst1, bsrc1 + kb);
        CP_COMMIT();
    }

    for (int kt = 0; kt < NT; kt++) {
        if (kt + 1 < NT) { CP_WAIT1(); } else { CP_WAIT0(); }
        __syncthreads();
        if (kt + 2 < NT) {
            int s = (kt + 2) % 3;
            int kb = (kt + 2) * BK;
            uint32_t so = (uint32_t)s * TILEB;
            cpasync16(sa + so + adst0, asrc0 + kb); cpasync16(sa + so + adst1, asrc1 + kb);
            cpasync16(sa + so + bdst0, bsrc0 + kb); cpasync16(sa + so + bdst1, bsrc1 + kb);
            CP_COMMIT();
        }
        uint32_t so = (uint32_t)(kt % 3) * TILEB;
        mma_ktile_ldsm(aBase + so, bBase + so, acc);
    }

    // epilogue: out[token] += wt * (acc + b2)
    int g = lane >> 2, t2 = (lane & 3) * 2;
    #pragma unroll
    for (int im = 0; im < 4; im++) {
        #pragma unroll
        for (int hf = 0; hf < 2; hf++) {
            int mloc = warp_m * 64 + im * 16 + g + hf * 8;
            if (m0 + mloc < cnt) {
                int pi = off + m0 + mloc;
                int tok = g_pair_token[pi];
                float wt = g_pair_w[pi];
                #pragma unroll
                for (int jn = 0; jn < 4; jn++) {
                    int n = n0 + warp_n * 32 + jn * 8 + t2;
                    float vx = wt * (acc[im][jn][hf * 2 + 0] + b2[e * D_DIM + n + 0]);
                    float vy = wt * (acc[im][jn][hf * 2 + 1] + b2[e * D_DIM + n + 1]);
                    atomicAdd(&out[(size_t)tok * D_DIM + n + 0], vx);
                    atomicAdd(&out[(size_t)tok * D_DIM + n + 1], vy);
                }
            }
        }
    }
}

// ---------------- launch: R14 structure + fused router tail --------------
extern "C" void kernel_launch(void* const* d_in, const int* in_sizes, int n_in,
                              void* d_out, int out_size) {
    const float* h   = (const float*)d_in[0];
    const float* gw1 = (const float*)d_in[1];
    const float* gb1 = (const float*)d_in[2];
    const float* gw2 = (const float*)d_in[3];
    const float* gb2 = (const float*)d_in[4];
    const float* gw3 = (const float*)d_in[5];
    const float* w1  = (const float*)d_in[6];
    const float* b1  = (const float*)d_in[7];
    const float* w2  = (const float*)d_in[8];
    const float* b2  = (const float*)d_in[9];
    (void)in_sizes; (void)n_in; (void)out_size;

    float* out = (float*)d_out;
    float* out_logits = out + (size_t)T_TOK * D_DIM;

    void *p_g1 = nullptr, *p_hh = nullptr, *p_w1t = nullptr, *p_w2t = nullptr;
    cudaGetSymbolAddress(&p_g1, g_g1);
    cudaGetSymbolAddress(&p_hh, g_hh);
    cudaGetSymbolAddress(&p_w1t, g_w1t);
    cudaGetSymbolAddress(&p_w2t, g_w2t);
    float*  g1  = (float*)p_g1;
    __half* hh  = (__half*)p_hh;
    __half* w1t = (__half*)p_w1t;
    __half* w2t = (__half*)p_w2t;

    // one-time host-side resources
    static bool init_done = false;
    static cudaStream_t sB = nullptr;
    static cudaEvent_t eFork = nullptr, eB = nullptr;
    if (!init_done) {
        cudaFuncSetAttribute(expert_g1_fp16, cudaFuncAttributeMaxDynamicSharedMemorySize, SMEM_EXP);
        cudaFuncSetAttribute(expert_g2_fp16, cudaFuncAttributeMaxDynamicSharedMemorySize, SMEM_EXP);
        cudaFuncSetAttribute(router_l2_fused, cudaFuncAttributeMaxDynamicSharedMemorySize, RT_SMEM);
        cudaStreamCreateWithFlags(&sB, cudaStreamNonBlocking);
        cudaEventCreateWithFlags(&eFork, cudaEventDisableTiming);
        cudaEventCreateWithFlags(&eB, cudaEventDisableTiming);
        init_done = true;
    }

    // --- serial front ---
    {
        int n4 = T_TOK * D_DIM / 4;
        f2h_kernel<<<(n4 + 255) / 256, 256>>>(h, hh, n4);
        transpose_f2h<<<dim3(F_DIM / 32, D_DIM / 32, E_NUM), dim3(32, 8)>>>(w1, w1t, D_DIM, F_DIM);
    }
    gemm64_bias_relu<<<dim3(G1_N / 64, T_TOK / 64), 256>>>(h, gw1, gb1, g1, T_TOK, G1_N, D_DIM);
    router_l2_fused<<<T_TOK / 64, 256, RT_SMEM>>>(g1, gw2, gb2, gw3, out_logits);
    build_pairs<<<1, 256>>>();

    // fork AFTER router chain: (t2 + zero) overlap gemm1 (tensor-bound)
    cudaEventRecord(eFork, 0);
    cudaStreamWaitEvent(sB, eFork, 0);
    transpose_f2h<<<dim3(D_DIM / 32, F_DIM / 32, E_NUM), dim3(32, 8), 0, sB>>>(w2, w2t, F_DIM, D_DIM);
    {
        int n4 = T_TOK * D_DIM / 4;
        zero_out_kernel<<<(n4 + 255) / 256, 256, 0, sB>>>(out, n4);
    }
    cudaEventRecord(eB, sB);

    // gemm1 concurrent with branch B
    expert_g1_fp16<<<dim3(F_DIM / 128, E_NUM * 32), 256, SMEM_EXP>>>(w1t, b1);
    cudaStreamWaitEvent(0, eB, 0);
    expert_g2_fp16<<<dim3(D_DIM / 128, E_NUM * 32), 256, SMEM_EXP>>>(w2t, b2, out);
}

// round 17
// speedup vs baseline: 1.0116x; 1.0116x over previous
#include <cuda_runtime.h>
#include <cuda_fp16.h>
#include <math.h>
#include <stdint.h>

// ---------------- problem constants ----------------
#define T_TOK 4096
#define D_DIM 1024
#define E_NUM 8
#define F_DIM 4096
#define G1_N  256
#define G2_N  64
#define MAXPAIRS (T_TOK * 2)

// ---------------- device scratch (no allocs allowed) ----------------
__device__ float  g_g1[T_TOK * G1_N];
__device__ __half g_acth[(size_t)MAXPAIRS * F_DIM];         // 64 MB fp16 activations
__device__ __half g_hh[(size_t)T_TOK * D_DIM];              // 8 MB fp16 hidden states
__device__ __half g_w1t[(size_t)E_NUM * F_DIM * D_DIM];     // 64 MB [e][F][D]
__device__ __half g_w2t[(size_t)E_NUM * D_DIM * F_DIM];     // 64 MB [e][D][F]
__device__ int    g_topi[T_TOK * 2];
__device__ float  g_topw[T_TOK * 2];
__device__ int    g_pair_token[MAXPAIRS];
__device__ float  g_pair_w[MAXPAIRS];
__device__ int    g_counts[E_NUM];
__device__ int    g_offsets[E_NUM];

// ---------------- helpers ----------------
__device__ __forceinline__ float gelu_tanh(float x) {
    float x3 = x * x * x;
    float u = 0.7978845608028654f * (x + 0.044715f * x3);
    return 0.5f * x * (1.0f + tanhf(u));
}

__device__ __forceinline__ uint32_t smem_u32(const void* p) {
    uint32_t a;
    asm("{ .reg .u64 t; cvta.to.shared.u64 t, %1; cvt.u32.u64 %0, t; }" : "=r"(a) : "l"(p));
    return a;
}

__device__ __forceinline__ void cpasync16(uint32_t s, const void* g) {
    asm volatile("cp.async.cg.shared.global [%0], [%1], 16;" :: "r"(s), "l"(g));
}
#define CP_COMMIT() asm volatile("cp.async.commit_group;" ::: "memory")
#define CP_WAIT0()  asm volatile("cp.async.wait_group 0;" ::: "memory")
#define CP_WAIT1()  asm volatile("cp.async.wait_group 1;" ::: "memory")

__device__ __forceinline__ void mma16816(float* d, const uint32_t* a, const uint32_t* b) {
    asm volatile(
        "mma.sync.aligned.m16n8k16.row.col.f32.f16.f16.f32 "
        "{%0,%1,%2,%3}, {%4,%5,%6,%7}, {%8,%9}, {%0,%1,%2,%3};\n"
        : "+f"(d[0]), "+f"(d[1]), "+f"(d[2]), "+f"(d[3])
        : "r"(a[0]), "r"(a[1]), "r"(a[2]), "r"(a[3]), "r"(b[0]), "r"(b[1]));
}

__device__ __forceinline__ void ldsm4(uint32_t& r0, uint32_t& r1, uint32_t& r2, uint32_t& r3,
                                      uint32_t addr) {
    asm volatile("ldmatrix.sync.aligned.m8n8.x4.shared.b16 {%0,%1,%2,%3}, [%4];"
                 : "=r"(r0), "=r"(r1), "=r"(r2), "=r"(r3) : "r"(addr));
}

// ---------------- zero output ----------------
__global__ void zero_out_kernel(float* __restrict__ out, int n4) {
    int i = blockIdx.x * blockDim.x + threadIdx.x;
    if (i < n4) ((float4*)out)[i] = make_float4(0.f, 0.f, 0.f, 0.f);
}

// ---------------- one-time fp32 -> fp16 conversions ----------------
__global__ void f2h_kernel(const float* __restrict__ in, __half* __restrict__ out, int n4) {
    int i = blockIdx.x * blockDim.x + threadIdx.x;
    if (i < n4) {
        float4 v = ((const float4*)in)[i];
        ((__half2*)out)[2 * i + 0] = __floats2half2_rn(v.x, v.y);
        ((__half2*)out)[2 * i + 1] = __floats2half2_rn(v.z, v.w);
    }
}

// batched transpose: in [R][C] fp32 row-major -> out [C][R] fp16 (z = batch)
__global__ void transpose_f2h(const float* __restrict__ in, __half* __restrict__ out,
                              int R, int C) {
    __shared__ float t[32][33];
    size_t base = (size_t)blockIdx.z * R * C;
    int x = blockIdx.x * 32 + threadIdx.x;
    int y = blockIdx.y * 32 + threadIdx.y;
    #pragma unroll
    for (int j = 0; j < 32; j += 8)
        t[threadIdx.y + j][threadIdx.x] = in[base + (size_t)(y + j) * C + x];
    __syncthreads();
    int ox = blockIdx.y * 32 + threadIdx.x;
    int oy = blockIdx.x * 32 + threadIdx.y;
    #pragma unroll
    for (int j = 0; j < 32; j += 8)
        out[base + (size_t)(oy + j) * R + ox] = __float2half_rn(t[threadIdx.x][threadIdx.y + j]);
}

// ---------------- router layer 1: exact fp32, 64x64 tiles ----------------
__global__ void __launch_bounds__(256)
gemm64_bias_relu(const float* __restrict__ A, const float* __restrict__ B,
                 const float* __restrict__ bias, float* __restrict__ C,
                 int M, int N, int K) {
    const int BKr = 16;
    __shared__ float As[BKr][64];
    __shared__ float Bs[BKr][64];
    int tid = threadIdx.x;
    int m0 = blockIdx.y * 64, n0 = blockIdx.x * 64;
    int tx = tid & 15, ty = tid >> 4;
    int arow = tid >> 2, ac4 = (tid & 3) * 4;
    int brow = tid >> 4, bc4 = (tid & 15) * 4;
    float acc[4][4];
    #pragma unroll
    for (int i = 0; i < 4; i++)
        #pragma unroll
        for (int j = 0; j < 4; j++) acc[i][j] = 0.f;

    const float* aptr = A + (size_t)(m0 + arow) * K + ac4;
    const float* bptr = B + (size_t)brow * N + n0 + bc4;
    for (int k0 = 0; k0 < K; k0 += BKr) {
        float4 av = *(const float4*)(aptr + k0);
        As[ac4 + 0][arow] = av.x; As[ac4 + 1][arow] = av.y;
        As[ac4 + 2][arow] = av.z; As[ac4 + 3][arow] = av.w;
        float4 bv = *(const float4*)(bptr + (size_t)k0 * N);
        *(float4*)&Bs[brow][bc4] = bv;
        __syncthreads();
        #pragma unroll
        for (int k = 0; k < BKr; k++) {
            float ra[4], rb[4];
            #pragma unroll
            for (int i = 0; i < 4; i++) ra[i] = As[k][ty * 4 + i];
            #pragma unroll
            for (int j = 0; j < 4; j++) rb[j] = Bs[k][tx * 4 + j];
            #pragma unroll
            for (int i = 0; i < 4; i++)
                #pragma unroll
                for (int j = 0; j < 4; j++) acc[i][j] = fmaf(ra[i], rb[j], acc[i][j]);
        }
        __syncthreads();
    }
    #pragma unroll
    for (int i = 0; i < 4; i++) {
        int m = m0 + ty * 4 + i;
        #pragma unroll
        for (int j = 0; j < 4; j++) {
            int n = n0 + tx * 4 + j;
            C[(size_t)m * N + n] = fmaxf(acc[i][j] + bias[n], 0.f);
        }
    }
}

// ---------------- fused router layer 2 + logits + top-2 (exact fp32) -----
// v2: 16 tokens/CTA, grid = T/16 = 256 CTAs, 256 threads.
// Smem: full gw2 [256][RT2_W2P] + g1 tile [16][RT2_G1P]  (~86 KB).
// 16 threads per token; each computes 4 contiguous n-outputs.
#define RT2_W2P 68
#define RT2_G1P 260
#define RT2_SMEM ((256 * RT2_W2P + 16 * RT2_G1P) * 4)

__global__ void __launch_bounds__(256)
router_l2_fused2(const float* __restrict__ g1, const float* __restrict__ gw2,
                 const float* __restrict__ gb2, const float* __restrict__ gw3,
                 float* __restrict__ out_logits) {
    extern __shared__ float sm[];
    float* sW2 = sm;                       // [256][RT2_W2P]
    float* sG1 = sm + 256 * RT2_W2P;       // [16][RT2_G1P]
    int tid = threadIdx.x;
    int tok0 = blockIdx.x * 16;
    int tok = tid >> 4;                    // 0..15
    int ng  = (tid & 15) * 4;              // base n (4 outputs per thread)

    // stage gw2: 256 rows x 16 float4
    for (int i = tid; i < 256 * 16; i += 256) {
        int r = i >> 4, c4 = i & 15;
        float4 v = *(const float4*)&gw2[(size_t)r * G2_N + c4 * 4];
        *(float4*)&sW2[r * RT2_W2P + c4 * 4] = v;
    }
    // stage g1 tile: 16 tokens x 64 float4
    for (int i = tid; i < 16 * 64; i += 256) {
        int r = i >> 6, c4 = i & 63;
        float4 v = *(const float4*)&g1[(size_t)(tok0 + r) * G1_N + c4 * 4];
        *(float4*)&sG1[r * RT2_G1P + c4 * 4] = v;
    }
    __syncthreads();

    float acc[4] = {0.f, 0.f, 0.f, 0.f};
    for (int k = 0; k < G1_N; k++) {
        float a = sG1[tok * RT2_G1P + k];
        float4 w = *(const float4*)&sW2[k * RT2_W2P + ng];
        acc[0] = fmaf(a, w.x, acc[0]);
        acc[1] = fmaf(a, w.y, acc[1]);
        acc[2] = fmaf(a, w.z, acc[2]);
        acc[3] = fmaf(a, w.w, acc[3]);
    }

    // g2 = relu(acc + gb2); partial logits over this thread's 4 n's
    float l[E_NUM];
    #pragma unroll
    for (int e = 0; e < E_NUM; e++) l[e] = 0.f;
    #pragma unroll
    for (int j = 0; j < 4; j++) {
        int n = ng + j;
        float v = fmaxf(acc[j] + gb2[n], 0.f);
        #pragma unroll
        for (int e = 0; e < E_NUM; e++)
            l[e] = fmaf(v, gw3[n * E_NUM + e], l[e]);
    }
    // reduce across the 16 lanes of this token (xor 1,2,4,8 stays in-group)
    #pragma unroll
    for (int e = 0; e < E_NUM; e++) {
        l[e] += __shfl_xor_sync(0xffffffffu, l[e], 1);
        l[e] += __shfl_xor_sync(0xffffffffu, l[e], 2);
        l[e] += __shfl_xor_sync(0xffffffffu, l[e], 4);
        l[e] += __shfl_xor_sync(0xffffffffu, l[e], 8);
    }
    if ((tid & 15) == 0) {
        int t = tok0 + tok;
        #pragma unroll
        for (int e = 0; e < E_NUM; e++) out_logits[(size_t)t * E_NUM + e] = l[e];
        int i0 = 0; float v0 = l[0];
        #pragma unroll
        for (int e = 1; e < E_NUM; e++) { if (l[e] > v0) { v0 = l[e]; i0 = e; } }
        int i1 = -1; float v1 = -3.4e38f;
        #pragma unroll
        for (int e = 0; e < E_NUM; e++) { if (e != i0 && l[e] > v1) { v1 = l[e]; i1 = e; } }
        float e1 = expf(v1 - v0);
        float inv = 1.f / (1.f + e1);
        g_topi[2 * t] = i0;  g_topi[2 * t + 1] = i1;
        g_topw[2 * t] = inv; g_topw[2 * t + 1] = e1 * inv;
    }
}

__global__ void build_pairs() {
    __shared__ int s_cnt[E_NUM];
    __shared__ int s_off[E_NUM];
    int tid = threadIdx.x, wid = tid >> 5, lane = tid & 31;
    if (wid < E_NUM) {
        int e = wid, cnt = 0;
        for (int base = 0; base < T_TOK; base += 32) {
            int t = base + lane;
            bool c = (g_topi[2 * t] == e) || (g_topi[2 * t + 1] == e);
            cnt += __popc(__ballot_sync(0xffffffffu, c));
        }
        if (lane == 0) s_cnt[e] = cnt;
    }
    __syncthreads();
    if (tid == 0) {
        int off = 0;
        for (int e = 0; e < E_NUM; e++) {
            s_off[e] = off; g_offsets[e] = off; g_counts[e] = s_cnt[e];
            off += s_cnt[e];
        }
    }
    __syncthreads();
    if (wid < E_NUM) {
        int e = wid, pos = s_off[e];
        for (int base = 0; base < T_TOK; base += 32) {
            int t = base + lane;
            bool c0 = (g_topi[2 * t] == e);
            bool c  = c0 || (g_topi[2 * t + 1] == e);
            unsigned b = __ballot_sync(0xffffffffu, c);
            int idx = pos + __popc(b & ((1u << lane) - 1u));
            if (c) {
                g_pair_token[idx] = t;
                g_pair_w[idx] = c0 ? g_topw[2 * t] : g_topw[2 * t + 1];
            }
            pos += __popc(b);
        }
    }
}

// ======================================================================
// fp16 mma.sync expert GEMMs, 3-stage cp.async pipeline + ldmatrix.
// CTA tile 128x128, BK=32, 8 warps (2m x 4n), warp tile 64x32.
// Dynamic smem: 3 stages x (A,B) 128x40 halves = 60 KB. 2 CTAs/SM.
// R7-proven loop: wait -> __syncthreads -> prefetch(kt+2) -> compute(kt).
// ======================================================================
#define BK   32
#define KPAD 40
#define TILEB (128 * KPAD * 2)            // bytes per operand per stage
#define SMEM_EXP (6 * TILEB)              // 3 stages x (A + B)

// one BK=32 k-tile of MMAs from stage buffers (ldmatrix fragments)
__device__ __forceinline__ void mma_ktile_ldsm(uint32_t aAddr, uint32_t bAddr,
                                               float acc[4][4][4]) {
    #pragma unroll
    for (int kk = 0; kk < BK; kk += 16) {
        uint32_t a[4][4], b[4][2];
        #pragma unroll
        for (int im = 0; im < 4; im++)
            ldsm4(a[im][0], a[im][1], a[im][2], a[im][3],
                  aAddr + (uint32_t)((im * 16 * KPAD + kk) * 2));
        ldsm4(b[0][0], b[0][1], b[1][0], b[1][1], bAddr + (uint32_t)(kk * 2));
        ldsm4(b[2][0], b[2][1], b[3][0], b[3][1],
              bAddr + (uint32_t)((16 * KPAD + kk) * 2));
        #pragma unroll
        for (int im = 0; im < 4; im++)
            #pragma unroll
            for (int jn = 0; jn < 4; jn++)
                mma16816(acc[im][jn], a[im], b[jn]);
    }
}

// ---------------- pass A: act = gelu(gather(hh) @ w1t[e]^T + b1[e]) ------
__global__ void __launch_bounds__(256, 2)
expert_g1_fp16(const __half* __restrict__ w1t, const float* __restrict__ b1) {
    extern __shared__ char smemraw[];
    int gt = blockIdx.y;
    int e = gt >> 5;
    int m0 = (gt & 31) * 128;
    int cnt = g_counts[e];
    if (m0 >= cnt) return;
    int off = g_offsets[e];
    int n0 = blockIdx.x * 128;
    const __half* Bt = w1t + (size_t)e * F_DIM * D_DIM;

    int tid = threadIdx.x, lane = tid & 31, wid = tid >> 5;
    int warp_m = wid & 1, warp_n = wid >> 1;
    uint32_t sa = smem_u32(smemraw);

    int c0 = tid * 2, c1 = tid * 2 + 1;
    int ar0 = c0 >> 2, ac0 = c0 & 3;
    int ar1 = c1 >> 2, ac1 = c1 & 3;
    int p0 = (m0 + ar0 < cnt) ? off + m0 + ar0 : off;
    int p1 = (m0 + ar1 < cnt) ? off + m0 + ar1 : off;
    const __half* asrc0 = g_hh + (size_t)g_pair_token[p0] * D_DIM + ac0 * 8;
    const __half* asrc1 = g_hh + (size_t)g_pair_token[p1] * D_DIM + ac1 * 8;
    const __half* bsrc0 = Bt + (size_t)(n0 + ar0) * D_DIM + ac0 * 8;
    const __half* bsrc1 = Bt + (size_t)(n0 + ar1) * D_DIM + ac1 * 8;
    uint32_t adst0 = (uint32_t)(ar0 * KPAD + ac0 * 8) * 2;
    uint32_t adst1 = (uint32_t)(ar1 * KPAD + ac1 * 8) * 2;
    uint32_t bdst0 = 3 * TILEB + (uint32_t)(ar0 * KPAD + ac0 * 8) * 2;
    uint32_t bdst1 = 3 * TILEB + (uint32_t)(ar1 * KPAD + ac1 * 8) * 2;

    int a_row = lane & 15;
    int a_colh = (lane >> 4) * 8;
    uint32_t aBase = sa + (uint32_t)(((warp_m * 64 + a_row) * KPAD + a_colh) * 2);
    int b_row = (lane & 7) + ((lane >> 4) & 1) * 8;
    int b_colh = ((lane >> 3) & 1) * 8;
    uint32_t bBase = sa + 3 * TILEB + (uint32_t)(((warp_n * 32 + b_row) * KPAD + b_colh) * 2);

    float acc[4][4][4];
    #pragma unroll
    for (int im = 0; im < 4; im++)
        #pragma unroll
        for (int jn = 0; jn < 4; jn++)
            #pragma unroll
            for (int q = 0; q < 4; q++) acc[im][jn][q] = 0.f;

    const int NT = D_DIM / BK;
    #pragma unroll
    for (int s = 0; s < 2; s++) {
        int kb = s * BK;
        uint32_t so = (uint32_t)s * TILEB;
        cpasync16(sa + so + adst0, asrc0 + kb); cpasync16(sa + so + adst1, asrc1 + kb);
        cpasync16(sa + so + bdst0, bsrc0 + kb); cpasync16(sa + so + bdst1, bsrc1 + kb);
        CP_COMMIT();
    }

    for (int kt = 0; kt < NT; kt++) {
        if (kt + 1 < NT) { CP_WAIT1(); } else { CP_WAIT0(); }
        __syncthreads();
        if (kt + 2 < NT) {
            int s = (kt + 2) % 3;
            int kb = (kt + 2) * BK;
            uint32_t so = (uint32_t)s * TILEB;
            cpasync16(sa + so + adst0, asrc0 + kb); cpasync16(sa + so + adst1, asrc1 + kb);
            cpasync16(sa + so + bdst0, bsrc0 + kb); cpasync16(sa + so + bdst1, bsrc1 + kb);
            CP_COMMIT();
        }
        uint32_t so = (uint32_t)(kt % 3) * TILEB;
        mma_ktile_ldsm(aBase + so, bBase + so, acc);
    }

    // epilogue: gelu(acc + b1) -> g_acth (fp16)
    int g = lane >> 2, t2 = (lane & 3) * 2;
    #pragma unroll
    for (int im = 0; im < 4; im++) {
        #pragma unroll
        for (int hf = 0; hf < 2; hf++) {
            int mloc = warp_m * 64 + im * 16 + g + hf * 8;
            if (m0 + mloc < cnt) {
                size_t pi = (size_t)(off + m0 + mloc);
                #pragma unroll
                for (int jn = 0; jn < 4; jn++) {
                    int n = n0 + warp_n * 32 + jn * 8 + t2;
                    float vx = acc[im][jn][hf * 2 + 0] + b1[e * F_DIM + n + 0];
                    float vy = acc[im][jn][hf * 2 + 1] + b1[e * F_DIM + n + 1];
                    *(__half2*)&g_acth[pi * F_DIM + n] =
                        __floats2half2_rn(gelu_tanh(vx), gelu_tanh(vy));
                }
            }
        }
    }
}

// ---------------- pass B: out[token] += wt * (acth @ w2t[e]^T + b2[e]) ---
__global__ void __launch_bounds__(256, 2)
expert_g2_fp16(const __half* __restrict__ w2t, const float* __restrict__ b2,
               float* __restrict__ out) {
    extern __shared__ char smemraw[];
    int gt = blockIdx.y;
    int e = gt >> 5;
    int m0 = (gt & 31) * 128;
    int cnt = g_counts[e];
    if (m0 >= cnt) return;
    int off = g_offsets[e];
    int n0 = blockIdx.x * 128;
    const __half* Bt = w2t + (size_t)e * D_DIM * F_DIM;

    int tid = threadIdx.x, lane = tid & 31, wid = tid >> 5;
    int warp_m = wid & 1, warp_n = wid >> 1;
    uint32_t sa = smem_u32(smemraw);

    int c0 = tid * 2, c1 = tid * 2 + 1;
    int ar0 = c0 >> 2, ac0 = c0 & 3;
    int ar1 = c1 >> 2, ac1 = c1 & 3;
    size_t p0 = (size_t)((m0 + ar0 < cnt) ? off + m0 + ar0 : off);
    size_t p1 = (size_t)((m0 + ar1 < cnt) ? off + m0 + ar1 : off);
    const __half* asrc0 = g_acth + p0 * F_DIM + ac0 * 8;
    const __half* asrc1 = g_acth + p1 * F_DIM + ac1 * 8;
    const __half* bsrc0 = Bt + (size_t)(n0 + ar0) * F_DIM + ac0 * 8;
    const __half* bsrc1 = Bt + (size_t)(n0 + ar1) * F_DIM + ac1 * 8;
    uint32_t adst0 = (uint32_t)(ar0 * KPAD + ac0 * 8) * 2;
    uint32_t adst1 = (uint32_t)(ar1 * KPAD + ac1 * 8) * 2;
    uint32_t bdst0 = 3 * TILEB + (uint32_t)(ar0 * KPAD + ac0 * 8) * 2;
    uint32_t bdst1 = 3 * TILEB + (uint32_t)(ar1 * KPAD + ac1 * 8) * 2;

    int a_row = lane & 15;
    int a_colh = (lane >> 4) * 8;
    uint32_t aBase = sa + (uint32_t)(((warp_m * 64 + a_row) * KPAD + a_colh) * 2);
    int b_row = (lane & 7) + ((lane >> 4) & 1) * 8;
    int b_colh = ((lane >> 3) & 1) * 8;
    uint32_t bBase = sa + 3 * TILEB + (uint32_t)(((warp_n * 32 + b_row) * KPAD + b_colh) * 2);

    float acc[4][4][4];
    #pragma unroll
    for (int im = 0; im < 4; im++)
        #pragma unroll
        for (int jn = 0; jn < 4; jn++)
            #pragma unroll
            for (int q = 0; q < 4; q++) acc[im][jn][q] = 0.f;

    const int NT = F_DIM / BK;
    #pragma unroll
    for (int s = 0; s < 2; s++) {
        int kb = s * BK;
        uint32_t so = (uint32_t)s * TILEB;
        cpasync16(sa + so + adst0, asrc0 + kb); cpasync16(sa + so + adst1, asrc1 + kb);
        cpasync16(sa + so + bdst0, bsrc0 + kb); cpasync16(sa + so + bdst1, bsrc1 + kb);
        CP_COMMIT();
    }

    for (int kt = 0; kt < NT; kt++) {
        if (kt + 1 < NT) { CP_WAIT1(); } else { CP_WAIT0(); }
        __syncthreads();
        if (kt + 2 < NT) {
            int s = (kt + 2) % 3;
            int kb = (kt + 2) * BK;
            uint32_t so = (uint32_t)s * TILEB;
            cpasync16(sa + so + adst0, asrc0 + kb); cpasync16(sa + so + adst1, asrc1 + kb);
            cpasync16(sa + so + bdst0, bsrc0 + kb); cpasync16(sa + so + bdst1, bsrc1 + kb);
            CP_COMMIT();
        }
        uint32_t so = (uint32_t)(kt % 3) * TILEB;
        mma_ktile_ldsm(aBase + so, bBase + so, acc);
    }

    // epilogue: out[token] += wt * (acc + b2)
    int g = lane >> 2, t2 = (lane & 3) * 2;
    #pragma unroll
    for (int im = 0; im < 4; im++) {
        #pragma unroll
        for (int hf = 0; hf < 2; hf++) {
            int mloc = warp_m * 64 + im * 16 + g + hf * 8;
            if (m0 + mloc < cnt) {
                int pi = off + m0 + mloc;
                int tok = g_pair_token[pi];
                float wt = g_pair_w[pi];
                #pragma unroll
                for (int jn = 0; jn < 4; jn++) {
                    int n = n0 + warp_n * 32 + jn * 8 + t2;
                    float vx = wt * (acc[im][jn][hf * 2 + 0] + b2[e * D_DIM + n + 0]);
                    float vy = wt * (acc[im][jn][hf * 2 + 1] + b2[e * D_DIM + n + 1]);
                    atomicAdd(&out[(size_t)tok * D_DIM + n + 0], vx);
                    atomicAdd(&out[(size_t)tok * D_DIM + n + 1], vy);
                }
            }
        }
    }
}

// ---------------- launch: R14 structure + high-occupancy fused router ----
extern "C" void kernel_launch(void* const* d_in, const int* in_sizes, int n_in,
                              void* d_out, int out_size) {
    const float* h   = (const float*)d_in[0];
    const float* gw1 = (const float*)d_in[1];
    const float* gb1 = (const float*)d_in[2];
    const float* gw2 = (const float*)d_in[3];
    const float* gb2 = (const float*)d_in[4];
    const float* gw3 = (const float*)d_in[5];
    const float* w1  = (const float*)d_in[6];
    const float* b1  = (const float*)d_in[7];
    const float* w2  = (const float*)d_in[8];
    const float* b2  = (const float*)d_in[9];
    (void)in_sizes; (void)n_in; (void)out_size;

    float* out = (float*)d_out;
    float* out_logits = out + (size_t)T_TOK * D_DIM;

    void *p_g1 = nullptr, *p_hh = nullptr, *p_w1t = nullptr, *p_w2t = nullptr;
    cudaGetSymbolAddress(&p_g1, g_g1);
    cudaGetSymbolAddress(&p_hh, g_hh);
    cudaGetSymbolAddress(&p_w1t, g_w1t);
    cudaGetSymbolAddress(&p_w2t, g_w2t);
    float*  g1  = (float*)p_g1;
    __half* hh  = (__half*)p_hh;
    __half* w1t = (__half*)p_w1t;
    __half* w2t = (__half*)p_w2t;

    // one-time host-side resources
    static bool init_done = false;
    static cudaStream_t sB = nullptr;
    static cudaEvent_t eFork = nullptr, eB = nullptr;
    if (!init_done) {
        cudaFuncSetAttribute(expert_g1_fp16, cudaFuncAttributeMaxDynamicSharedMemorySize, SMEM_EXP);
        cudaFuncSetAttribute(expert_g2_fp16, cudaFuncAttributeMaxDynamicSharedMemorySize, SMEM_EXP);
        cudaFuncSetAttribute(router_l2_fused2, cudaFuncAttributeMaxDynamicSharedMemorySize, RT2_SMEM);
        cudaStreamCreateWithFlags(&sB, cudaStreamNonBlocking);
        cudaEventCreateWithFlags(&eFork, cudaEventDisableTiming);
        cudaEventCreateWithFlags(&eB, cudaEventDisableTiming);
        init_done = true;
    }

    // --- serial front ---
    {
        int n4 = T_TOK * D_DIM / 4;
        f2h_kernel<<<(n4 + 255) / 256, 256>>>(h, hh, n4);
        transpose_f2h<<<dim3(F_DIM / 32, D_DIM / 32, E_NUM), dim3(32, 8)>>>(w1, w1t, D_DIM, F_DIM);
    }
    gemm64_bias_relu<<<dim3(G1_N / 64, T_TOK / 64), 256>>>(h, gw1, gb1, g1, T_TOK, G1_N, D_DIM);
    router_l2_fused2<<<T_TOK / 16, 256, RT2_SMEM>>>(g1, gw2, gb2, gw3, out_logits);
    build_pairs<<<1, 256>>>();

    // fork AFTER router chain: (t2 + zero) overlap gemm1 (tensor-bound)
    cudaEventRecord(eFork, 0);
    cudaStreamWaitEvent(sB, eFork, 0);
    transpose_f2h<<<dim3(D_DIM / 32, F_DIM / 32, E_NUM), dim3(32, 8), 0, sB>>>(w2, w2t, F_DIM, D_DIM);
    {
        int n4 = T_TOK * D_DIM / 4;
        zero_out_kernel<<<(n4 + 255) / 256, 256, 0, sB>>>(out, n4);
    }
    cudaEventRecord(eB, sB);

    // gemm1 concurrent with branch B
    expert_g1_fp16<<<dim3(F_DIM / 128, E_NUM * 32), 256, SMEM_EXP>>>(w1t, b1);
    cudaStreamWaitEvent(0, eB, 0);
    expert_g2_fp16<<<dim3(D_DIM / 128, E_NUM * 32), 256, SMEM_EXP>>>(w2t, b2, out);
}